// round 1
// baseline (speedup 1.0000x reference)
#include <cuda_runtime.h>
#include <math.h>

// Problem constants (fixed shapes per setup_inputs)
#define BB 16
#define NAH 3          // anchors in mask [0..2]
#define HH 76
#define WW 76
#define HW (HH*WW)     // 5776
#define PP (NAH*HW)    // 17328
#define NC 80
#define CH 85
#define TT 20

__constant__ float c_aw[9] = {10.f,16.f,33.f,30.f,62.f,59.f,116.f,156.f,373.f};
__constant__ float c_ah[9] = {13.f,30.f,23.f,61.f,45.f,119.f,90.f,198.f,326.f};

__device__ double g_acc[3];   // [loc, conf, cls]

__global__ void zero_acc_k() {
    if (threadIdx.x < 3) g_acc[threadIdx.x] = 0.0;
}

__global__ void finalize_k(float* __restrict__ out) {
    if (threadIdx.x < 3) out[threadIdx.x] = (float)(g_acc[threadIdx.x] / (double)BB);
}

__global__ __launch_bounds__(256)
void yolo_main_k(const float* __restrict__ x, const float* __restrict__ tgt) {
    // Per-batch target match state (recomputed per block; T is tiny)
    __shared__ float s_t[TT*5];
    __shared__ int   s_flat[TT];
    __shared__ float s_tx[TT], s_ty[TT], s_twt[TT], s_tht[TT], s_sc[TT];
    __shared__ int   s_cls[TT];
    __shared__ float s_g1x[TT], s_g1y[TT], s_g2x[TT], s_g2y[TT], s_ga[TT];
    __shared__ int   s_val[TT];

    const int b   = blockIdx.y;
    const int tid = threadIdx.x;

    if (tid < TT*5) s_t[tid] = tgt[b*TT*5 + tid];
    __syncthreads();

    if (tid < TT) {
        const float wn = s_t[tid*5+2], hn = s_t[tid*5+3];
        const float cx = s_t[tid*5+0]*608.f, cy = s_t[tid*5+1]*608.f;
        const float gw = wn*608.f,           gh = hn*608.f;
        const int valid = (wn > 0.f);
        s_val[tid] = valid;
        s_g1x[tid] = cx - 0.5f*gw;  s_g2x[tid] = cx + 0.5f*gw;
        s_g1y[tid] = cy - 0.5f*gh;  s_g2y[tid] = cy + 0.5f*gh;
        s_ga[tid]  = gw*gh;
        // anchor IoU argmax (first max wins, matching jnp.argmax)
        float bestv = -1.f; int best = 0;
        #pragma unroll
        for (int k = 0; k < 9; k++) {
            float inter = fminf(gw, c_aw[k]) * fminf(gh, c_ah[k]);
            float v = inter / (gw*gh + c_aw[k]*c_ah[k] - inter + 1e-9f);
            if (v > bestv) { bestv = v; best = k; }
        }
        const int ok = valid && (best <= 2);
        const float gxs = cx * 0.125f, gys = cy * 0.125f;   // /stride, exact
        int gi = (int)floorf(gxs); gi = min(max(gi, 0), WW-1);
        int gj = (int)floorf(gys); gj = min(max(gj, 0), HH-1);
        s_flat[tid] = ok ? (best*HW + gj*WW + gi) : -1;
        s_tx[tid]  = gxs - (float)gi;
        s_ty[tid]  = gys - (float)gj;
        s_twt[tid] = logf(gw / c_aw[best]);
        s_tht[tid] = logf(gh / c_ah[best]);
        s_sc[tid]  = 2.f - wn*hn;
        s_cls[tid] = (int)s_t[tid*5+4];
    }
    __syncthreads();

    const int pos = blockIdx.x*256 + tid;
    float confL = 0.f, locL = 0.f, clsL = 0.f;

    if (pos < PP) {
        const int a    = pos / HW;
        const int cell = pos - a*HW;
        const int j    = cell / WW;
        const int i    = cell - j*WW;
        const size_t off = ((size_t)(b*NAH + a)*CH)*HW + (size_t)cell;

        // only 5/85 channels streamed for non-fore positions
        const float rx = x[off];
        const float ry = x[off +   (size_t)HW];
        const float rw = x[off + 2*(size_t)HW];
        const float rh = x[off + 3*(size_t)HW];
        const float rc = x[off + 4*(size_t)HW];

        const float sx = 1.f/(1.f+expf(-rx));
        const float sy = 1.f/(1.f+expf(-ry));

        // decode box (px) for ignore-mask IoU
        const float dcx = (sx + (float)i)*8.f;
        const float dcy = (sy + (float)j)*8.f;
        const float dw  = expf(rw)*c_aw[a];
        const float dh  = expf(rh)*c_ah[a];
        const float d1x = dcx - 0.5f*dw, d2x = dcx + 0.5f*dw;
        const float d1y = dcy - 0.5f*dh, d2y = dcy + 0.5f*dh;
        const float da  = dw*dh;

        float mx = 0.f;
        for (int t = 0; t < TT; t++) {
            if (!s_val[t]) continue;
            float iw = fmaxf(fminf(d2x, s_g2x[t]) - fmaxf(d1x, s_g1x[t]), 0.f);
            float ih = fmaxf(fminf(d2y, s_g2y[t]) - fmaxf(d1y, s_g1y[t]), 0.f);
            float inter = iw*ih;
            mx = fmaxf(mx, inter / (da + s_ga[t] - inter + 1e-9f));
        }

        // fore lookup: last-wins over scatter duplicates
        int e = -1;
        for (int t = TT-1; t >= 0; t--) {
            if (s_flat[t] == pos) { e = t; break; }
        }

        float pc = 1.f/(1.f+expf(-rc));
        pc = fminf(fmaxf(pc, 1e-12f), 1.f - 1e-12f);

        if (e >= 0) {
            confL = -logf(pc);
            const float w2 = s_sc[e];
            const float d0 = sx - s_tx[e],  d1 = sy - s_ty[e];
            const float d2 = rw - s_twt[e], d3 = rh - s_tht[e];
            locL = 0.5f*w2*(d0*d0 + d1*d1) + 0.5f*w2*(d2*d2 + d3*d3);
            const int cc = s_cls[e];
            for (int c = 0; c < NC; c++) {
                float rv = x[off + (size_t)(5+c)*HW];
                float pv = 1.f/(1.f+expf(-rv));
                pv = fminf(fmaxf(pv, 1e-12f), 1.f - 1e-12f);
                clsL += (c == cc) ? -logf(pv) : -logf(1.f - pv);
            }
        } else if (!(mx > 0.5f)) {
            confL = -logf(1.f - pc);   // background term
        }
    }

    // Block tree-reduce in double, then one atomicAdd per block per loss
    __shared__ double sred[256];
    double vals[3] = { (double)locL, (double)confL, (double)clsL };
    #pragma unroll
    for (int k = 0; k < 3; k++) {
        sred[tid] = vals[k];
        __syncthreads();
        for (int s = 128; s > 0; s >>= 1) {
            if (tid < s) sred[tid] += sred[tid + s];
            __syncthreads();
        }
        if (tid == 0) atomicAdd(&g_acc[k], sred[0]);
        __syncthreads();
    }
}

extern "C" void kernel_launch(void* const* d_in, const int* in_sizes, int n_in,
                              void* d_out, int out_size) {
    const float* x = (const float*)d_in[0];
    const float* t = (const float*)d_in[1];
    float* out = (float*)d_out;

    zero_acc_k<<<1, 32>>>();
    dim3 grid((PP + 255)/256, BB);
    yolo_main_k<<<grid, 256>>>(x, t);
    finalize_k<<<1, 32>>>(out);
}

// round 2
// speedup vs baseline: 2.0317x; 2.0317x over previous
#include <cuda_runtime.h>
#include <math.h>

#define BB 16
#define NAH 3
#define HH 76
#define WW 76
#define HW (HH*WW)     // 5776 (div by 4)
#define PP (NAH*HW)    // 17328
#define NC 80
#define CH 85
#define TT 20
#define BLK 128
#define GX 34          // ceil((PP/4)/BLK) = ceil(4332/128)
#define NBLK (GX*BB)   // 544

__constant__ float c_aw[9] = {10.f,16.f,33.f,30.f,62.f,59.f,116.f,156.f,373.f};
__constant__ float c_ah[9] = {13.f,30.f,23.f,61.f,45.f,119.f,90.f,198.f,326.f};

__device__ double   g_acc[3];       // statically zero; returns to zero every run
__device__ unsigned g_ticket = 0;   // wraps back to 0 every run via atomicInc

__device__ __forceinline__ float ex2f(float x){ float y; asm("ex2.approx.f32 %0,%1;" : "=f"(y) : "f"(x)); return y; }
__device__ __forceinline__ float lg2f(float x){ float y; asm("lg2.approx.f32 %0,%1;" : "=f"(y) : "f"(x)); return y; }
__device__ __forceinline__ float tanha(float x){ float y; asm("tanh.approx.f32 %0,%1;" : "=f"(y) : "f"(x)); return y; }

#define L2E 1.4426950408889634f
#define LN2 0.6931471805599453f

__device__ __forceinline__ float fexp(float x)     { return ex2f(x * L2E); }
__device__ __forceinline__ float fsigmoid(float x) { return fmaf(0.5f, tanha(0.5f*x), 0.5f); }
// softplus(z) = log(1+exp(z)) ; equals -log(sigmoid(-z)) / -log(1-sigmoid(z))
__device__ __forceinline__ float fsoftplus(float z){ return LN2 * lg2f(1.f + ex2f(z * L2E)); }

__global__ __launch_bounds__(BLK)
void yolo_k(const float* __restrict__ x, const float* __restrict__ tgt,
            float* __restrict__ out)
{
    __shared__ float s_g1x[TT], s_g1y[TT], s_g2x[TT], s_g2y[TT], s_thr[TT];
    __shared__ int   s_flat[TT];
    __shared__ float s_tx[TT], s_ty[TT], s_tw[TT], s_th[TT], s_sc[TT];
    __shared__ int   s_cls[TT];

    const int b   = blockIdx.y;
    const int tid = threadIdx.x;

    // ---- per-batch target matching (tiny; recomputed per block) ----
    if (tid < TT) {
        const float* tr = tgt + (size_t)(b*TT + tid)*5;
        const float wn = tr[2], hn = tr[3];
        const float cx = tr[0]*608.f, cy = tr[1]*608.f;
        const float gw = wn*608.f,    gh = hn*608.f;
        const bool valid = (wn > 0.f);
        if (valid) {
            s_g1x[tid] = cx - 0.5f*gw;  s_g2x[tid] = cx + 0.5f*gw;
            s_g1y[tid] = cy - 0.5f*gh;  s_g2y[tid] = cy + 0.5f*gh;
            s_thr[tid] = gw*gh + 1e-9f;          // test: 3*inter - thr > da
        } else {
            s_g1x[tid] =  1e30f; s_g2x[tid] = -1e30f;
            s_g1y[tid] =  1e30f; s_g2y[tid] = -1e30f;
            s_thr[tid] =  1e30f;
        }
        // anchor-IoU argmax over 9 anchors (first max wins, as jnp.argmax)
        float bestv = -1.f; int best = 0;
        #pragma unroll
        for (int k = 0; k < 9; k++) {
            float inter = fminf(gw, c_aw[k]) * fminf(gh, c_ah[k]);
            float v = inter / (gw*gh + c_aw[k]*c_ah[k] - inter + 1e-9f);
            if (v > bestv) { bestv = v; best = k; }
        }
        const bool ok = valid && (best <= 2);
        const float gxs = cx * 0.125f, gys = cy * 0.125f;
        int gi = (int)floorf(gxs); gi = min(max(gi, 0), WW-1);
        int gj = (int)floorf(gys); gj = min(max(gj, 0), HH-1);
        s_flat[tid] = ok ? (best*HW + gj*WW + gi) : -1;
        s_tx[tid] = gxs - (float)gi;
        s_ty[tid] = gys - (float)gj;
        s_tw[tid] = logf(gw / c_aw[best]);
        s_th[tid] = logf(gh / c_ah[best]);
        s_sc[tid] = 2.f - wn*hn;
        s_cls[tid] = (int)tr[4];
    }
    __syncthreads();

    float accL = 0.f, accC = 0.f, accS = 0.f;

    const int lin  = blockIdx.x*BLK + tid;
    const int pos4 = lin*4;
    if (pos4 < PP) {
        const int a    = pos4 / HW;           // pack never crosses anchor (HW%4==0)
        const int cell = pos4 - a*HW;
        const int j    = cell / WW;           // pack never crosses row (WW%4==0)
        const int i0   = cell - j*WW;
        const size_t off = ((size_t)(b*NAH + a)*CH)*HW + (size_t)cell;

        const float4 RX = *(const float4*)(x + off);
        const float4 RY = *(const float4*)(x + off +   (size_t)HW);
        const float4 RW = *(const float4*)(x + off + 2*(size_t)HW);
        const float4 RH = *(const float4*)(x + off + 3*(size_t)HW);
        const float4 RC = *(const float4*)(x + off + 4*(size_t)HW);
        const float rx[4] = {RX.x,RX.y,RX.z,RX.w};
        const float ry[4] = {RY.x,RY.y,RY.z,RY.w};
        const float rw[4] = {RW.x,RW.y,RW.z,RW.w};
        const float rh[4] = {RH.x,RH.y,RH.z,RH.w};
        const float rc[4] = {RC.x,RC.y,RC.z,RC.w};

        const float aw = c_aw[a], ah = c_ah[a];

        float sx[4], sy[4], d1x[4], d2x[4], d1y[4], d2y[4], da[4];
        #pragma unroll
        for (int s = 0; s < 4; s++) {
            sx[s] = fsigmoid(rx[s]);
            sy[s] = fsigmoid(ry[s]);
            const float dw  = fexp(rw[s]) * aw;
            const float dh  = fexp(rh[s]) * ah;
            const float dcx = (sx[s] + (float)(i0 + s)) * 8.f;
            const float dcy = (sy[s] + (float)j) * 8.f;
            d1x[s] = dcx - 0.5f*dw;  d2x[s] = dcx + 0.5f*dw;
            d1y[s] = dcy - 0.5f*dh;  d2y[s] = dcy + 0.5f*dh;
            da[s]  = dw*dh;
        }

        bool ign[4] = {false,false,false,false};
        int  e[4]   = {-1,-1,-1,-1};

        #pragma unroll
        for (int t = 0; t < TT; t++) {
            const float g1x = s_g1x[t], g2x = s_g2x[t];
            const float g1y = s_g1y[t], g2y = s_g2y[t];
            const float thr = s_thr[t];
            const int   fl  = s_flat[t] - pos4;
            #pragma unroll
            for (int s = 0; s < 4; s++) {
                const float iw = fmaxf(fminf(d2x[s], g2x) - fmaxf(d1x[s], g1x), 0.f);
                const float ih = fmaxf(fminf(d2y[s], g2y) - fmaxf(d1y[s], g1y), 0.f);
                const float inter = iw*ih;
                ign[s] |= (fmaf(3.f, inter, -thr) > da[s]);  // iou > 0.5 (no div)
                if (fl == s) e[s] = t;                        // last-wins scatter
            }
        }

        #pragma unroll
        for (int s = 0; s < 4; s++) {
            if (e[s] >= 0) {
                accC += fsoftplus(-rc[s]);                 // -log(sigmoid)
                const int t = e[s];
                const float w2 = s_sc[t];
                const float d0 = sx[s] - s_tx[t], d1 = sy[s] - s_ty[t];
                const float d2 = rw[s] - s_tw[t], d3 = rh[s] - s_th[t];
                accL += 0.5f*w2*(d0*d0 + d1*d1) + 0.5f*w2*(d2*d2 + d3*d3);
                const int cc = s_cls[t];
                for (int c = 0; c < NC; c++) {
                    const float rv = x[off + (size_t)s + (size_t)(5+c)*HW];
                    accS += (c == cc) ? fsoftplus(-rv) : fsoftplus(rv);
                }
            } else if (!ign[s]) {
                accC += fsoftplus(rc[s]);                  // -log(1-sigmoid)
            }
        }
    }

    // ---- block reduction (double), one atomicAdd per block per loss ----
    double v0 = (double)accL, v1 = (double)accC, v2 = (double)accS;
    #pragma unroll
    for (int o = 16; o > 0; o >>= 1) {
        v0 += __shfl_down_sync(0xffffffffu, v0, o);
        v1 += __shfl_down_sync(0xffffffffu, v1, o);
        v2 += __shfl_down_sync(0xffffffffu, v2, o);
    }
    __shared__ double sred[3][BLK/32];
    const int w = tid >> 5, l = tid & 31;
    if (l == 0) { sred[0][w] = v0; sred[1][w] = v1; sred[2][w] = v2; }
    __syncthreads();
    if (tid == 0) {
        double t0 = 0.0, t1 = 0.0, t2 = 0.0;
        #pragma unroll
        for (int k = 0; k < BLK/32; k++) { t0 += sred[0][k]; t1 += sred[1][k]; t2 += sred[2][k]; }
        atomicAdd(&g_acc[0], t0);
        atomicAdd(&g_acc[1], t1);
        atomicAdd(&g_acc[2], t2);
        __threadfence();
        const unsigned old = atomicInc(&g_ticket, NBLK - 1);   // wraps to 0 each run
        if (old == NBLK - 1) {
            #pragma unroll
            for (int k = 0; k < 3; k++) {
                // read-and-reset: leaves g_acc at 0 for the next graph replay
                unsigned long long raw = atomicExch((unsigned long long*)&g_acc[k], 0ull);
                out[k] = (float)(__longlong_as_double(raw) / (double)BB);
            }
        }
    }
}

extern "C" void kernel_launch(void* const* d_in, const int* in_sizes, int n_in,
                              void* d_out, int out_size) {
    const float* x = (const float*)d_in[0];
    const float* t = (const float*)d_in[1];
    float* out = (float*)d_out;
    dim3 grid(GX, BB);
    yolo_k<<<grid, BLK>>>(x, t, out);
}

// round 3
// speedup vs baseline: 2.1361x; 1.0514x over previous
#include <cuda_runtime.h>
#include <math.h>

#define BB 16
#define NAH 3
#define HH 76
#define WW 76
#define HW (HH*WW)     // 5776 (even)
#define PP (NAH*HW)    // 17328
#define NC 80
#define CH 85
#define TT 20
#define BLK 128
#define PPT 2
#define GX  ((PP/PPT + BLK - 1)/BLK)   // 68
#define NBLK (GX*BB)                   // 1088

__constant__ float c_aw[9] = {10.f,16.f,33.f,30.f,62.f,59.f,116.f,156.f,373.f};
__constant__ float c_ah[9] = {13.f,30.f,23.f,61.f,45.f,119.f,90.f,198.f,326.f};

__device__ double   g_acc[3];       // statically zero; returned to zero every run
__device__ unsigned g_ticket = 0;   // wraps to 0 every run via atomicInc

__device__ __forceinline__ float ex2f(float x){ float y; asm("ex2.approx.f32 %0,%1;" : "=f"(y) : "f"(x)); return y; }
__device__ __forceinline__ float lg2f(float x){ float y; asm("lg2.approx.f32 %0,%1;" : "=f"(y) : "f"(x)); return y; }
__device__ __forceinline__ float tanha(float x){ float y; asm("tanh.approx.f32 %0,%1;" : "=f"(y) : "f"(x)); return y; }

#define L2E 1.4426950408889634f
#define LN2 0.6931471805599453f

__device__ __forceinline__ float fexp(float x)     { return ex2f(x * L2E); }
__device__ __forceinline__ float fsigmoid(float x) { return fmaf(0.5f, tanha(0.5f*x), 0.5f); }
__device__ __forceinline__ float fsoftplus(float z){ return LN2 * lg2f(1.f + ex2f(z * L2E)); }

__global__ __launch_bounds__(BLK)
void yolo_k(const float* __restrict__ x, const float* __restrict__ tgt,
            float* __restrict__ out)
{
    // raw (per-slot) match results
    __shared__ float r_g1x[TT], r_g1y[TT], r_g2x[TT], r_g2y[TT], r_thr[TT];
    __shared__ int   r_flat[TT], r_valid[TT];
    __shared__ float r_tx[TT], r_ty[TT], r_tw[TT], r_th[TT], r_sc[TT];
    __shared__ int   r_cls[TT];
    // compacted (valid-only, order preserved)
    __shared__ float s_g1x[TT], s_g1y[TT], s_g2x[TT], s_g2y[TT], s_thr[TT];
    __shared__ int   s_flat[TT];
    __shared__ float s_tx[TT], s_ty[TT], s_tw[TT], s_th[TT], s_sc[TT];
    __shared__ int   s_cls[TT];
    __shared__ int   s_nv;

    const int b   = blockIdx.y;
    const int tid = threadIdx.x;

    if (tid < TT) {
        const float* tr = tgt + (size_t)(b*TT + tid)*5;
        const float wn = tr[2], hn = tr[3];
        const float cx = tr[0]*608.f, cy = tr[1]*608.f;
        const float gw = wn*608.f,    gh = hn*608.f;
        r_valid[tid] = (wn > 0.f);
        r_g1x[tid] = cx - 0.5f*gw;  r_g2x[tid] = cx + 0.5f*gw;
        r_g1y[tid] = cy - 0.5f*gh;  r_g2y[tid] = cy + 0.5f*gh;
        r_thr[tid] = gw*gh + 1e-9f;               // ign test: 3*inter - thr > da
        // anchor-IoU argmax over 9 anchors (first max wins)
        float bestv = -1.f; int best = 0;
        #pragma unroll
        for (int k = 0; k < 9; k++) {
            float inter = fminf(gw, c_aw[k]) * fminf(gh, c_ah[k]);
            float v = inter / (gw*gh + c_aw[k]*c_ah[k] - inter + 1e-9f);
            if (v > bestv) { bestv = v; best = k; }
        }
        const bool ok = r_valid[tid] && (best <= 2);
        const float gxs = cx * 0.125f, gys = cy * 0.125f;
        int gi = (int)floorf(gxs); gi = min(max(gi, 0), WW-1);
        int gj = (int)floorf(gys); gj = min(max(gj, 0), HH-1);
        r_flat[tid] = ok ? (best*HW + gj*WW + gi) : -1;
        r_tx[tid] = gxs - (float)gi;
        r_ty[tid] = gys - (float)gj;
        r_tw[tid] = logf(gw / c_aw[best]);
        r_th[tid] = logf(gh / c_ah[best]);
        r_sc[tid] = 2.f - wn*hn;
        r_cls[tid] = (int)tr[4];
    }
    __syncthreads();
    if (tid == 0) {
        int nv = 0;
        for (int t = 0; t < TT; t++) {
            if (r_valid[t]) {
                s_g1x[nv]=r_g1x[t]; s_g2x[nv]=r_g2x[t];
                s_g1y[nv]=r_g1y[t]; s_g2y[nv]=r_g2y[t];
                s_thr[nv]=r_thr[t]; s_flat[nv]=r_flat[t];
                s_tx[nv]=r_tx[t];   s_ty[nv]=r_ty[t];
                s_tw[nv]=r_tw[t];   s_th[nv]=r_th[t];
                s_sc[nv]=r_sc[t];   s_cls[nv]=r_cls[t];
                nv++;
            }
        }
        s_nv = nv;
    }
    __syncthreads();
    const int nv = s_nv;

    float accL = 0.f, accC = 0.f, accS = 0.f;

    const int lin  = blockIdx.x*BLK + tid;
    const int pos2 = lin*PPT;
    if (pos2 < PP) {
        const int a    = pos2 / HW;          // pack never crosses anchor (HW even)
        const int cell = pos2 - a*HW;
        const int j    = cell / WW;          // pack never crosses row (WW even)
        const int i0   = cell - j*WW;
        const size_t off = ((size_t)(b*NAH + a)*CH)*HW + (size_t)cell;

        const float2 RX = *(const float2*)(x + off);
        const float2 RY = *(const float2*)(x + off +   (size_t)HW);
        const float2 RW = *(const float2*)(x + off + 2*(size_t)HW);
        const float2 RH = *(const float2*)(x + off + 3*(size_t)HW);
        const float2 RC = *(const float2*)(x + off + 4*(size_t)HW);
        const float rx[2] = {RX.x,RX.y};
        const float ry[2] = {RY.x,RY.y};
        const float rw[2] = {RW.x,RW.y};
        const float rh[2] = {RH.x,RH.y};
        const float rc[2] = {RC.x,RC.y};

        const float aw = c_aw[a], ah = c_ah[a];

        float sx[2], sy[2], d1x[2], d2x[2], d1y[2], d2y[2], da[2];
        #pragma unroll
        for (int s = 0; s < PPT; s++) {
            sx[s] = fsigmoid(rx[s]);
            sy[s] = fsigmoid(ry[s]);
            const float dw  = fexp(rw[s]) * aw;
            const float dh  = fexp(rh[s]) * ah;
            const float dcx = (sx[s] + (float)(i0 + s)) * 8.f;
            const float dcy = (sy[s] + (float)j) * 8.f;
            d1x[s] = dcx - 0.5f*dw;  d2x[s] = dcx + 0.5f*dw;
            d1y[s] = dcy - 0.5f*dh;  d2y[s] = dcy + 0.5f*dh;
            da[s]  = dw*dh;
        }

        // ---- hot loop: ignore-mask IoU test only (no divisions) ----
        bool ign[2] = {false,false};
        #pragma unroll 5
        for (int t = 0; t < nv; t++) {
            const float g1x = s_g1x[t], g2x = s_g2x[t];
            const float g1y = s_g1y[t], g2y = s_g2y[t];
            const float thr = s_thr[t];
            #pragma unroll
            for (int s = 0; s < PPT; s++) {
                const float iw = fmaxf(fminf(d2x[s], g2x) - fmaxf(d1x[s], g1x), 0.f);
                const float ih = fmaxf(fminf(d2y[s], g2y) - fmaxf(d1y[s], g1y), 0.f);
                const float inter = iw*ih;
                ign[s] |= (fmaf(3.f, inter, -thr) > da[s]);   // iou > 0.5
            }
        }

        // ---- fore lookup (last-wins over scatter duplicates) ----
        int e[2] = {-1,-1};
        for (int t = 0; t < nv; t++) {
            const int fl = s_flat[t] - pos2;
            #pragma unroll
            for (int s = 0; s < PPT; s++) if (fl == s) e[s] = t;
        }

        #pragma unroll
        for (int s = 0; s < PPT; s++) {
            if (e[s] >= 0) {
                accC += fsoftplus(-rc[s]);              // -log(sigmoid)
                const int t = e[s];
                const float w2 = s_sc[t];
                const float d0 = sx[s] - s_tx[t], d1 = sy[s] - s_ty[t];
                const float d2 = rw[s] - s_tw[t], d3 = rh[s] - s_th[t];
                accL += 0.5f*w2*(d0*d0 + d1*d1) + 0.5f*w2*(d2*d2 + d3*d3);
                const int cc = s_cls[t];
                for (int c = 0; c < NC; c++) {
                    const float rv = x[off + (size_t)s + (size_t)(5+c)*HW];
                    accS += (c == cc) ? fsoftplus(-rv) : fsoftplus(rv);
                }
            } else if (!ign[s]) {
                accC += fsoftplus(rc[s]);               // -log(1-sigmoid)
            }
        }
    }

    // ---- block reduction (double), one atomicAdd per block per loss ----
    double v0 = (double)accL, v1 = (double)accC, v2 = (double)accS;
    #pragma unroll
    for (int o = 16; o > 0; o >>= 1) {
        v0 += __shfl_down_sync(0xffffffffu, v0, o);
        v1 += __shfl_down_sync(0xffffffffu, v1, o);
        v2 += __shfl_down_sync(0xffffffffu, v2, o);
    }
    __shared__ double sred[3][BLK/32];
    const int w = tid >> 5, l = tid & 31;
    if (l == 0) { sred[0][w] = v0; sred[1][w] = v1; sred[2][w] = v2; }
    __syncthreads();
    if (tid == 0) {
        double t0 = 0.0, t1 = 0.0, t2 = 0.0;
        #pragma unroll
        for (int k = 0; k < BLK/32; k++) { t0 += sred[0][k]; t1 += sred[1][k]; t2 += sred[2][k]; }
        atomicAdd(&g_acc[0], t0);
        atomicAdd(&g_acc[1], t1);
        atomicAdd(&g_acc[2], t2);
        __threadfence();
        const unsigned old = atomicInc(&g_ticket, NBLK - 1);   // wraps to 0 each run
        if (old == NBLK - 1) {
            #pragma unroll
            for (int k = 0; k < 3; k++) {
                unsigned long long raw = atomicExch((unsigned long long*)&g_acc[k], 0ull);
                out[k] = (float)(__longlong_as_double(raw) / (double)BB);
            }
        }
    }
}

extern "C" void kernel_launch(void* const* d_in, const int* in_sizes, int n_in,
                              void* d_out, int out_size) {
    const float* x = (const float*)d_in[0];
    const float* t = (const float*)d_in[1];
    float* out = (float*)d_out;
    dim3 grid(GX, BB);
    yolo_k<<<grid, BLK>>>(x, t, out);
}

// round 4
// speedup vs baseline: 2.3198x; 1.0860x over previous
#include <cuda_runtime.h>
#include <math.h>

#define BB 16
#define NAH 3
#define HH 76
#define WW 76
#define HW (HH*WW)     // 5776 (even)
#define PP (NAH*HW)    // 17328
#define NC 80
#define CH 85
#define TT 20
#define BLK 128
#define PPT 2
#define GX  ((PP/PPT + BLK - 1)/BLK)   // 68
#define NBLK (GX*BB)                   // 1088

__constant__ float c_aw[9] = {10.f,16.f,33.f,30.f,62.f,59.f,116.f,156.f,373.f};
__constant__ float c_ah[9] = {13.f,30.f,23.f,61.f,45.f,119.f,90.f,198.f,326.f};

__device__ double   g_acc[3];       // statically zero; returned to zero every run
__device__ unsigned g_ticket = 0;   // wraps to 0 every run via atomicInc

__device__ __forceinline__ float ex2f(float x){ float y; asm("ex2.approx.f32 %0,%1;" : "=f"(y) : "f"(x)); return y; }
__device__ __forceinline__ float lg2f(float x){ float y; asm("lg2.approx.f32 %0,%1;" : "=f"(y) : "f"(x)); return y; }
__device__ __forceinline__ float tanha(float x){ float y; asm("tanh.approx.f32 %0,%1;" : "=f"(y) : "f"(x)); return y; }

#define L2E 1.4426950408889634f
#define LN2 0.6931471805599453f

__device__ __forceinline__ float fexp(float x)     { return ex2f(x * L2E); }
__device__ __forceinline__ float fsigmoid(float x) { return fmaf(0.5f, tanha(0.5f*x), 0.5f); }
__device__ __forceinline__ float fsoftplus(float z){ return LN2 * lg2f(1.f + ex2f(z * L2E)); }

__global__ __launch_bounds__(BLK)
void yolo_k(const float* __restrict__ x, const float* __restrict__ tgt,
            float* __restrict__ out)
{
    // fixed-slot target data; invalid slots carry inert sentinels (no compaction)
    __shared__ float s_g1x[TT], s_g1y[TT], s_g2x[TT], s_g2y[TT], s_thr[TT];
    __shared__ int   s_flat[TT];
    __shared__ float s_tx[TT], s_ty[TT], s_tw[TT], s_th[TT], s_sc[TT];
    __shared__ int   s_cls[TT];

    const int b   = blockIdx.y;
    const int tid = threadIdx.x;

    if (tid < TT) {
        const float* tr = tgt + (size_t)(b*TT + tid)*5;
        const float wn = tr[2], hn = tr[3];
        const float cx = tr[0]*608.f, cy = tr[1]*608.f;
        const float gw = wn*608.f,    gh = hn*608.f;
        const bool valid = (wn > 0.f);
        if (valid) {
            s_g1x[tid] = cx - 0.5f*gw;  s_g2x[tid] = cx + 0.5f*gw;
            s_g1y[tid] = cy - 0.5f*gh;  s_g2y[tid] = cy + 0.5f*gh;
            s_thr[tid] = gw*gh + 1e-9f;           // ign test: 3*inter - thr > da
        } else {
            s_g1x[tid] =  1e30f; s_g2x[tid] = -1e30f;   // inert: inter -> 0
            s_g1y[tid] =  1e30f; s_g2y[tid] = -1e30f;
            s_thr[tid] =  1e30f;                        // -thr never beats da
        }
        // anchor-IoU argmax over 9 anchors (first max wins, as jnp.argmax)
        float bestv = -1.f; int best = 0;
        #pragma unroll
        for (int k = 0; k < 9; k++) {
            float inter = fminf(gw, c_aw[k]) * fminf(gh, c_ah[k]);
            float v = inter / (gw*gh + c_aw[k]*c_ah[k] - inter + 1e-9f);
            if (v > bestv) { bestv = v; best = k; }
        }
        const bool ok = valid && (best <= 2);
        const float gxs = cx * 0.125f, gys = cy * 0.125f;
        int gi = (int)floorf(gxs); gi = min(max(gi, 0), WW-1);
        int gj = (int)floorf(gys); gj = min(max(gj, 0), HH-1);
        s_flat[tid] = ok ? (best*HW + gj*WW + gi) : -1;    // -1 never matches
        s_tx[tid] = gxs - (float)gi;
        s_ty[tid] = gys - (float)gj;
        s_tw[tid] = logf(fmaxf(gw, 1e-30f) / c_aw[best]);  // unused when !ok
        s_th[tid] = logf(fmaxf(gh, 1e-30f) / c_ah[best]);
        s_sc[tid] = 2.f - wn*hn;
        s_cls[tid] = (int)tr[4];
    }
    __syncthreads();

    float accL = 0.f, accC = 0.f, accS = 0.f;

    const int lin  = blockIdx.x*BLK + tid;
    const int pos2 = lin*PPT;
    if (pos2 < PP) {
        const int a    = pos2 / HW;          // pack never crosses anchor (HW even)
        const int cell = pos2 - a*HW;
        const int j    = cell / WW;          // pack never crosses row (WW even)
        const int i0   = cell - j*WW;
        const size_t off = ((size_t)(b*NAH + a)*CH)*HW + (size_t)cell;

        const float2 RX = *(const float2*)(x + off);
        const float2 RY = *(const float2*)(x + off +   (size_t)HW);
        const float2 RW = *(const float2*)(x + off + 2*(size_t)HW);
        const float2 RH = *(const float2*)(x + off + 3*(size_t)HW);
        const float2 RC = *(const float2*)(x + off + 4*(size_t)HW);
        const float rx[2] = {RX.x,RX.y};
        const float ry[2] = {RY.x,RY.y};
        const float rw[2] = {RW.x,RW.y};
        const float rh[2] = {RH.x,RH.y};
        const float rc[2] = {RC.x,RC.y};

        const float aw = c_aw[a], ah = c_ah[a];

        float sx[2], sy[2], d1x[2], d2x[2], d1y[2], d2y[2], da[2];
        #pragma unroll
        for (int s = 0; s < PPT; s++) {
            sx[s] = fsigmoid(rx[s]);
            sy[s] = fsigmoid(ry[s]);
            const float dw  = fexp(rw[s]) * aw;
            const float dh  = fexp(rh[s]) * ah;
            const float dcx = (sx[s] + (float)(i0 + s)) * 8.f;
            const float dcy = (sy[s] + (float)j) * 8.f;
            d1x[s] = dcx - 0.5f*dw;  d2x[s] = dcx + 0.5f*dw;
            d1y[s] = dcy - 0.5f*dh;  d2y[s] = dcy + 0.5f*dh;
            da[s]  = dw*dh;
        }

        // ---- hot loop: fully unrolled, fixed trip; LDS gets batched (MLP) ----
        bool ign[2] = {false,false};
        int  e[2]   = {-1,-1};
        #pragma unroll
        for (int t = 0; t < TT; t++) {
            const float g1x = s_g1x[t], g2x = s_g2x[t];
            const float g1y = s_g1y[t], g2y = s_g2y[t];
            const float thr = s_thr[t];
            const int   fl  = s_flat[t] - pos2;
            #pragma unroll
            for (int s = 0; s < PPT; s++) {
                const float iw = fmaxf(fminf(d2x[s], g2x) - fmaxf(d1x[s], g1x), 0.f);
                const float ih = fmaxf(fminf(d2y[s], g2y) - fmaxf(d1y[s], g1y), 0.f);
                const float inter = iw*ih;
                ign[s] |= (fmaf(3.f, inter, -thr) > da[s]);   // iou > 0.5, no div
                if (fl == s) e[s] = t;                         // last-wins scatter
            }
        }

        #pragma unroll
        for (int s = 0; s < PPT; s++) {
            if (e[s] >= 0) {
                accC += fsoftplus(-rc[s]);              // -log(sigmoid)
                const int t = e[s];
                const float w2 = s_sc[t];
                const float d0 = sx[s] - s_tx[t], d1 = sy[s] - s_ty[t];
                const float d2 = rw[s] - s_tw[t], d3 = rh[s] - s_th[t];
                accL += 0.5f*w2*(d0*d0 + d1*d1) + 0.5f*w2*(d2*d2 + d3*d3);
                const int cc = s_cls[t];
                for (int c = 0; c < NC; c++) {
                    const float rv = x[off + (size_t)s + (size_t)(5+c)*HW];
                    accS += (c == cc) ? fsoftplus(-rv) : fsoftplus(rv);
                }
            } else if (!ign[s]) {
                accC += fsoftplus(rc[s]);               // -log(1-sigmoid)
            }
        }
    }

    // ---- block reduction (double), one atomicAdd per block per loss ----
    double v0 = (double)accL, v1 = (double)accC, v2 = (double)accS;
    #pragma unroll
    for (int o = 16; o > 0; o >>= 1) {
        v0 += __shfl_down_sync(0xffffffffu, v0, o);
        v1 += __shfl_down_sync(0xffffffffu, v1, o);
        v2 += __shfl_down_sync(0xffffffffu, v2, o);
    }
    __shared__ double sred[3][BLK/32];
    const int w = tid >> 5, l = tid & 31;
    if (l == 0) { sred[0][w] = v0; sred[1][w] = v1; sred[2][w] = v2; }
    __syncthreads();
    if (tid == 0) {
        double t0 = 0.0, t1 = 0.0, t2 = 0.0;
        #pragma unroll
        for (int k = 0; k < BLK/32; k++) { t0 += sred[0][k]; t1 += sred[1][k]; t2 += sred[2][k]; }
        atomicAdd(&g_acc[0], t0);
        atomicAdd(&g_acc[1], t1);
        atomicAdd(&g_acc[2], t2);
        __threadfence();
        const unsigned old = atomicInc(&g_ticket, NBLK - 1);   // wraps to 0 each run
        if (old == NBLK - 1) {
            #pragma unroll
            for (int k = 0; k < 3; k++) {
                unsigned long long raw = atomicExch((unsigned long long*)&g_acc[k], 0ull);
                out[k] = (float)(__longlong_as_double(raw) / (double)BB);
            }
        }
    }
}

extern "C" void kernel_launch(void* const* d_in, const int* in_sizes, int n_in,
                              void* d_out, int out_size) {
    const float* x = (const float*)d_in[0];
    const float* t = (const float*)d_in[1];
    float* out = (float*)d_out;
    dim3 grid(GX, BB);
    yolo_k<<<grid, BLK>>>(x, t, out);
}